// round 5
// baseline (speedup 1.0000x reference)
#include <cuda_runtime.h>
#include <math.h>

#define BATCH      262144
#define IN_DIM     96
#define HID        32
#define D          16
#define K_OTHERS   15
#define N_FOOD     16
#define LN_EPS     1e-5f
#define ATT_SCALE  0.25f        // 1/sqrt(16)

#define TPB        128

typedef unsigned long long u64;

// ---------------- packed f32x2 helpers (sm_100+ PTX) ----------------
__device__ __forceinline__ u64 pack2(float lo, float hi) {
    u64 r;
    asm("mov.b64 %0, {%1, %2};" : "=l"(r) : "f"(lo), "f"(hi));
    return r;
}
__device__ __forceinline__ void unpack2(u64 v, float& lo, float& hi) {
    asm("mov.b64 {%0, %1}, %2;" : "=f"(lo), "=f"(hi) : "l"(v));
}
__device__ __forceinline__ u64 fma2(u64 a, u64 b, u64 c) {
    u64 d;
    asm("fma.rn.f32x2 %0, %1, %2, %3;" : "=l"(d) : "l"(a), "l"(b), "l"(c));
    return d;
}
__device__ __forceinline__ u64 mul2(u64 a, u64 b) {
    u64 d;
    asm("mul.rn.f32x2 %0, %1, %2;" : "=l"(d) : "l"(a), "l"(b));
    return d;
}
__device__ __forceinline__ u64 relu2(u64 v) {
    float a, b;
    unpack2(v, a, b);
    return pack2(fmaxf(a, 0.f), fmaxf(b, 0.f));
}

// ---- shared-memory weight layout (float offsets, all 16B aligned) ----
#define ENW1 0      // 128  (4 x 32)
#define ENB1 128    // 32
#define ENW2 160    // 512  (32 x 16)
#define ENB2 672    // 16
#define OAW1 688    // 128
#define OAB1 816    // 32
#define OAW2 848    // 512
#define OAB2 1360   // 16
#define GW1  1376   // 64   (2 x 32)
#define GB1  1440   // 32
#define GW2  1472   // 512
#define GB2  1984   // 16
#define OLNG 2000   // 16
#define OLNB 2016   // 16
#define GLNG 2032   // 16
#define GLNB 2048   // 16
#define AW1  2064   // 1536 (48 x 32)
#define AB1  3600   // 32
#define AW2  3632   // 1024 (32 x 32)
#define AB2  4656   // 32
#define AW3  4688   // 64   (32 x 2)
#define AB3  4752   // 2 (+pad)
#define SW_TOTAL 4768

__device__ __forceinline__ void cpyw(float* dst, const float* __restrict__ src,
                                     int n, int tid) {
    for (int i = tid; i < n; i += TPB) dst[i] = src[i];
}

// x[IN] -> relu(x@W1+b1) (32) -> relu(h@W2+b2) -> out8 = 8 packed f32x2 (16 floats)
template <int IN>
__device__ __forceinline__ void encode2(const float* __restrict__ x,
                                        const float* __restrict__ W1,
                                        const float* __restrict__ b1,
                                        const float* __restrict__ W2,
                                        const float* __restrict__ b2,
                                        u64* __restrict__ out8) {
    u64 h[16];
    {
        const u64* bv = (const u64*)b1;
        #pragma unroll
        for (int j = 0; j < 16; j++) h[j] = bv[j];
    }
    #pragma unroll
    for (int i = 0; i < IN; i++) {
        u64 xx = pack2(x[i], x[i]);
        const ulonglong2* wv = (const ulonglong2*)(W1 + i * HID);
        #pragma unroll
        for (int j = 0; j < 8; j++) {
            ulonglong2 w = wv[j];
            h[2*j+0] = fma2(xx, w.x, h[2*j+0]);
            h[2*j+1] = fma2(xx, w.y, h[2*j+1]);
        }
    }
    // relu + unpack to scalars (broadcast multiplicands for layer 2)
    float hs[HID];
    #pragma unroll
    for (int j = 0; j < 16; j++) {
        float a, b;
        unpack2(h[j], a, b);
        hs[2*j+0] = fmaxf(a, 0.f);
        hs[2*j+1] = fmaxf(b, 0.f);
    }
    u64 o[8];
    {
        const u64* bv = (const u64*)b2;
        #pragma unroll
        for (int d = 0; d < 8; d++) o[d] = bv[d];
    }
    #pragma unroll
    for (int j = 0; j < HID; j++) {
        u64 hh = pack2(hs[j], hs[j]);
        const ulonglong2* wv = (const ulonglong2*)(W2 + j * D);
        #pragma unroll
        for (int d = 0; d < 4; d++) {
            ulonglong2 w = wv[d];
            o[2*d+0] = fma2(hh, w.x, o[2*d+0]);
            o[2*d+1] = fma2(hh, w.y, o[2*d+1]);
        }
    }
    #pragma unroll
    for (int d = 0; d < 8; d++) out8[d] = relu2(o[d]);
}

// pool (16 floats, scalar) -> y = relu(LN(pool)*g+b), scalar out
__device__ __forceinline__ void ln_relu(const float* __restrict__ x,
                                        const float* __restrict__ g,
                                        const float* __restrict__ b,
                                        float* __restrict__ y) {
    float s = 0.f;
    #pragma unroll
    for (int d = 0; d < D; d++) s += x[d];
    float mu = s * (1.f / D);
    float v = 0.f;
    #pragma unroll
    for (int d = 0; d < D; d++) { float c = x[d] - mu; v = fmaf(c, c, v); }
    float inv = rsqrtf(v * (1.f / D) + LN_EPS);
    #pragma unroll
    for (int d = 0; d < D; d++)
        y[d] = fmaxf(fmaf((x[d] - mu) * inv, g[d], b[d]), 0.f);
}

// online-softmax attention step over one encoded agent; updates (m, ss, acc8)
__device__ __forceinline__ void attend_step(const u64* __restrict__ e8,
                                            const u64* __restrict__ self8,
                                            float& m, float& ss,
                                            u64* __restrict__ acc8) {
    // score = dot(self, e) * ATT_SCALE
    u64 d2 = mul2(self8[0], e8[0]);
    #pragma unroll
    for (int d = 1; d < 8; d++) d2 = fma2(self8[d], e8[d], d2);
    float sa, sb;
    unpack2(d2, sa, sb);
    float sc = (sa + sb) * ATT_SCALE;

    float nm   = fmaxf(m, sc);
    float corr = __expf(m - nm);   // first iter: exp(-inf)=0
    float w    = __expf(sc - nm);
    ss = fmaf(ss, corr, w);
    u64 c2 = pack2(corr, corr);
    u64 w2 = pack2(w, w);
    #pragma unroll
    for (int d = 0; d < 8; d++)
        acc8[d] = fma2(acc8[d], c2, mul2(w2, e8[d]));
    m = nm;
}

// merged-segment contribution to head layer-1 accumulators h[16] (packed)
__device__ __forceinline__ void head_seg(const float* __restrict__ xi,
                                         const float* __restrict__ W,  // 16 x 32
                                         u64* __restrict__ h) {
    #pragma unroll
    for (int i = 0; i < D; i++) {
        u64 xx = pack2(xi[i], xi[i]);
        const ulonglong2* wv = (const ulonglong2*)(W + i * HID);
        #pragma unroll
        for (int j = 0; j < 8; j++) {
            ulonglong2 w = wv[j];
            h[2*j+0] = fma2(xx, w.x, h[2*j+0]);
            h[2*j+1] = fma2(xx, w.y, h[2*j+1]);
        }
    }
}

__global__ void __launch_bounds__(TPB)
actor_kernel(const float* __restrict__ s,
             const float* __restrict__ enW1, const float* __restrict__ enb1,
             const float* __restrict__ enW2, const float* __restrict__ enb2,
             const float* __restrict__ oaW1, const float* __restrict__ oab1,
             const float* __restrict__ oaW2, const float* __restrict__ oab2,
             const float* __restrict__ gW1,  const float* __restrict__ gb1,
             const float* __restrict__ gW2,  const float* __restrict__ gb2,
             const float* __restrict__ olng, const float* __restrict__ olnb,
             const float* __restrict__ glng, const float* __restrict__ glnb,
             const float* __restrict__ aW1,  const float* __restrict__ ab1,
             const float* __restrict__ aW2,  const float* __restrict__ ab2,
             const float* __restrict__ aW3,  const float* __restrict__ ab3,
             float* __restrict__ out) {
    __shared__ float sw[SW_TOTAL];
    const int tid = threadIdx.x;

    cpyw(sw + ENW1, enW1, 128, tid);  cpyw(sw + ENB1, enb1, 32, tid);
    cpyw(sw + ENW2, enW2, 512, tid);  cpyw(sw + ENB2, enb2, 16, tid);
    cpyw(sw + OAW1, oaW1, 128, tid);  cpyw(sw + OAB1, oab1, 32, tid);
    cpyw(sw + OAW2, oaW2, 512, tid);  cpyw(sw + OAB2, oab2, 16, tid);
    cpyw(sw + GW1,  gW1,  64,  tid);  cpyw(sw + GB1,  gb1,  32, tid);
    cpyw(sw + GW2,  gW2,  512, tid);  cpyw(sw + GB2,  gb2,  16, tid);
    cpyw(sw + OLNG, olng, 16,  tid);  cpyw(sw + OLNB, olnb, 16, tid);
    cpyw(sw + GLNG, glng, 16,  tid);  cpyw(sw + GLNB, glnb, 16, tid);
    cpyw(sw + AW1,  aW1,  1536, tid); cpyw(sw + AB1,  ab1,  32, tid);
    cpyw(sw + AW2,  aW2,  1024, tid); cpyw(sw + AB2,  ab2,  32, tid);
    cpyw(sw + AW3,  aW3,  64,  tid);  cpyw(sw + AB3,  ab3,  2,  tid);
    __syncthreads();

    const int r = blockIdx.x * TPB + tid;
    const float* __restrict__ row = s + (size_t)r * IN_DIM;

    // ---------------- self encoder ----------------
    u64 self8[8];
    {
        float4 x4 = *(const float4*)row;
        float xin[4] = {x4.x, x4.y, x4.z, x4.w};
        encode2<4>(xin, sw + ENW1, sw + ENB1, sw + ENW2, sw + ENB2, self8);
    }

    // ---------------- other-agent attention (online softmax) ----------------
    float other_pool[D];
    {
        u64 acc8[8];
        #pragma unroll
        for (int d = 0; d < 8; d++) acc8[d] = 0ull;   // packed (0,0)
        float m = -INFINITY, ss = 0.f;
        #pragma unroll 1        // keep body rolled: ~400 instr x 15 would blow I$
        for (int k = 0; k < K_OTHERS; k++) {
            float2 a = *(const float2*)(row + 4 + 2 * k);
            float2 b = *(const float2*)(row + 4 + 2 * K_OTHERS + 2 * k);
            float xin[4] = {a.x, a.y, b.x, b.y};
            u64 e8[8];
            encode2<4>(xin, sw + OAW1, sw + OAB1, sw + OAW2, sw + OAB2, e8);
            attend_step(e8, self8, m, ss, acc8);
        }
        float inv = 1.f / ss;
        float pool[D];
        #pragma unroll
        for (int d = 0; d < 8; d++) {
            float a, b;
            unpack2(acc8[d], a, b);
            pool[2*d+0] = a * inv;
            pool[2*d+1] = b * inv;
        }
        ln_relu(pool, sw + OLNG, sw + OLNB, other_pool);
    }

    // ---------------- food attention ----------------
    float food_pool[D];
    {
        u64 acc8[8];
        #pragma unroll
        for (int d = 0; d < 8; d++) acc8[d] = 0ull;
        float m = -INFINITY, ss = 0.f;
        #pragma unroll 1        // keep body rolled (I$)
        for (int k = 0; k < N_FOOD; k++) {
            float2 a = *(const float2*)(row + IN_DIM - 2 * N_FOOD + 2 * k);
            float xin[2] = {a.x, a.y};
            u64 e8[8];
            encode2<2>(xin, sw + GW1, sw + GB1, sw + GW2, sw + GB2, e8);
            attend_step(e8, self8, m, ss, acc8);
        }
        float inv = 1.f / ss;
        float pool[D];
        #pragma unroll
        for (int d = 0; d < 8; d++) {
            float a, b;
            unpack2(acc8[d], a, b);
            pool[2*d+0] = a * inv;
            pool[2*d+1] = b * inv;
        }
        ln_relu(pool, sw + GLNG, sw + GLNB, food_pool);
    }

    // self_out scalars for head input
    float self_out[D];
    #pragma unroll
    for (int d = 0; d < 8; d++)
        unpack2(self8[d], self_out[2*d], self_out[2*d+1]);

    // ---------------- actor head: merged = [self, food, other] ----------------
    float hs1[HID];
    {
        u64 h[16];
        const u64* bv = (const u64*)(sw + AB1);
        #pragma unroll
        for (int j = 0; j < 16; j++) h[j] = bv[j];

        head_seg(self_out,   sw + AW1,            h);
        head_seg(food_pool,  sw + AW1 + D * HID,  h);
        head_seg(other_pool, sw + AW1 + 2*D*HID,  h);

        #pragma unroll
        for (int j = 0; j < 16; j++) {
            float a, b;
            unpack2(h[j], a, b);
            hs1[2*j+0] = (a > 0.f) ? a : 0.01f * a;
            hs1[2*j+1] = (b > 0.f) ? b : 0.01f * b;
        }
    }

    float hs2[HID];
    {
        u64 h[16];
        const u64* bv = (const u64*)(sw + AB2);
        #pragma unroll
        for (int j = 0; j < 16; j++) h[j] = bv[j];
        #pragma unroll
        for (int i = 0; i < HID; i++) {
            u64 xx = pack2(hs1[i], hs1[i]);
            const ulonglong2* wv = (const ulonglong2*)(sw + AW2 + i * HID);
            #pragma unroll
            for (int j = 0; j < 8; j++) {
                ulonglong2 w = wv[j];
                h[2*j+0] = fma2(xx, w.x, h[2*j+0]);
                h[2*j+1] = fma2(xx, w.y, h[2*j+1]);
            }
        }
        #pragma unroll
        for (int j = 0; j < 16; j++) {
            float a, b;
            unpack2(h[j], a, b);
            hs2[2*j+0] = (a > 0.f) ? a : 0.01f * a;
            hs2[2*j+1] = (b > 0.f) ? b : 0.01f * b;
        }
    }

    // final 32 -> 2: rows of AW3 are exactly (w0, w1) pairs -> packed accumulate
    u64 o2 = *(const u64*)(sw + AB3);
    {
        const u64* wv = (const u64*)(sw + AW3);
        #pragma unroll
        for (int j = 0; j < HID; j++)
            o2 = fma2(pack2(hs2[j], hs2[j]), wv[j], o2);
    }
    float o0, o1;
    unpack2(o2, o0, o1);

    float2 res;
    res.x = tanhf(o0);   // exact libm tanh: 2 calls/thread, precision safety
    res.y = tanhf(o1);
    *(float2*)(out + (size_t)2 * r) = res;
}

extern "C" void kernel_launch(void* const* d_in, const int* in_sizes, int n_in,
                              void* d_out, int out_size) {
    (void)in_sizes; (void)n_in; (void)out_size;
    actor_kernel<<<BATCH / TPB, TPB>>>(
        (const float*)d_in[0],
        (const float*)d_in[1],  (const float*)d_in[2],
        (const float*)d_in[3],  (const float*)d_in[4],
        (const float*)d_in[5],  (const float*)d_in[6],
        (const float*)d_in[7],  (const float*)d_in[8],
        (const float*)d_in[9],  (const float*)d_in[10],
        (const float*)d_in[11], (const float*)d_in[12],
        (const float*)d_in[13], (const float*)d_in[14],
        (const float*)d_in[15], (const float*)d_in[16],
        (const float*)d_in[17], (const float*)d_in[18],
        (const float*)d_in[19], (const float*)d_in[20],
        (const float*)d_in[21], (const float*)d_in[22],
        (float*)d_out);
}